// round 6
// baseline (speedup 1.0000x reference)
#include <cuda_runtime.h>
#include <cstdint>

#define DI __device__ __forceinline__

namespace {

constexpr int E_N  = 8;
constexpr int D_IN = 512;
constexpr int H_N  = 256;
constexpr int T_N  = 64;
constexpr int BM   = 128;        // batch rows per CTA
constexpr int NT   = 256;        // threads per CTA (8 warps)
constexpr int KC   = 32;         // fp32 elements per K chunk
constexpr int NCH  = D_IN / KC;  // 16 chunks per expert

// ---- smem layout (bytes) ----
// Region0 holds either the two raw chunk buffers or the Y tile (phases exclusive).
// chunk buffer: A[128][36] f32 (18432 B) + W[256][36] f32 (36864 B) = 55296 B
constexpr int BUF_SZ  = 55296;
constexpr int OFF_A0  = 0;
constexpr int OFF_W0  = 18432;
constexpr int OFF_A1  = BUF_SZ;              // 55296
constexpr int OFF_W1  = BUF_SZ + 18432;      // 73728  (ends 110592)
constexpr int OFF_Y   = 0;                   // Y [128][260] f32 = 133120 B
constexpr int REGION0 = 133120;
constexpr int OFF_WT  = REGION0;             // Wt tf32 [64][260] = 66560
constexpr int OFF_WG  = REGION0 + 66560;     // Wg fp32 [8][512]  = 16384
constexpr int OFF_GATE= REGION0 + 82944;     // gate [128][8] f32 = 4096
constexpr int SMEM_SZ = REGION0 + 87040;     // 220160 bytes

DI uint32_t smem_u32(const void* p) {
  uint32_t a;
  asm("{ .reg .u64 t; cvta.to.shared.u64 t, %1; cvt.u32.u64 %0, t; }"
      : "=r"(a) : "l"(p));
  return a;
}
DI uint32_t f2tf(float f) {
  uint32_t r;
  asm("cvt.rna.tf32.f32 %0, %1;" : "=r"(r) : "f"(f));
  return r;
}
DI float sigmoidf_(float x) { return 1.0f / (1.0f + __expf(-x)); }

DI void cp16(uint32_t sdst, const void* gsrc) {
  asm volatile("cp.async.cg.shared.global [%0], [%1], 16;"
               ::"r"(sdst), "l"(gsrc) : "memory");
}
DI void cp_commit() { asm volatile("cp.async.commit_group;" ::: "memory"); }
template <int N>
DI void cp_wait() { asm volatile("cp.async.wait_group %0;" ::"n"(N) : "memory"); }

// mma.sync m16n8k8 tf32: D += A*B (A row-major 16x8, B col-major 8x8)
DI void mma_s(float& d0, float& d1, float& d2, float& d3,
              uint32_t a0, uint32_t a1, uint32_t a2, uint32_t a3,
              uint32_t b0, uint32_t b1) {
  asm volatile(
      "mma.sync.aligned.m16n8k8.row.col.f32.tf32.tf32.f32 "
      "{%0,%1,%2,%3},{%4,%5,%6,%7},{%8,%9},{%0,%1,%2,%3};"
      : "+f"(d0), "+f"(d1), "+f"(d2), "+f"(d3)
      : "r"(a0), "r"(a1), "r"(a2), "r"(a3), "r"(b0), "r"(b1));
}

}  // namespace

extern __shared__ char smem[];

__global__ void __launch_bounds__(NT, 1)
mmoe_fused_kernel(const float* __restrict__ xv, const float* __restrict__ We,
                  const float* __restrict__ be, const float* __restrict__ Wg,
                  const float* __restrict__ bg, const float* __restrict__ Wt,
                  const float* __restrict__ bt, float* __restrict__ out) {
  const int tid = threadIdx.x;
  const int wid = tid >> 5;
  const int lid = tid & 31;
  const int g   = lid >> 2;   // 0..7
  const int t4  = lid & 3;    // 0..3
  const int wm  = wid & 1;    // M group of 64 rows (main GEMM)
  const int wn  = wid >> 1;   // N group of 64 cols (main GEMM)
  const int twm = wid & 3;    // M group of 32 rows (tower)
  const int twn = wid >> 2;   // T group of 32 cols (tower)
  const int row0 = blockIdx.x * BM;
  const float* Abase = xv + (size_t)row0 * D_IN;

  const uint32_t sb = smem_u32(smem);
  float* gsm = (float*)(smem + OFF_GATE);
  const float* Ysf = (const float*)(smem + OFF_Y);
  const uint32_t* Ysu = (const uint32_t*)(smem + OFF_Y);
  uint32_t* Yw = (uint32_t*)(smem + OFF_Y);
  const uint32_t* WTu = (const uint32_t*)(smem + OFF_WT);

  // ---- Stage Wt [64,256] -> tf32 [64][260] and Wg [8,512] fp32 ----
  for (int i4 = tid; i4 < (T_N * H_N) / 4; i4 += NT) {
    int t = i4 >> 6, kq = i4 & 63;
    float4 v = *(const float4*)(Wt + (size_t)t * H_N + kq * 4);
    uint32_t* dst = (uint32_t*)(smem + OFF_WT) + t * 260 + kq * 4;
    dst[0] = f2tf(v.x); dst[1] = f2tf(v.y); dst[2] = f2tf(v.z); dst[3] = f2tf(v.w);
  }
  for (int i4 = tid; i4 < (E_N * D_IN) / 4; i4 += NT)
    *(float4*)(smem + OFF_WG + i4 * 16) = *(const float4*)(Wg + i4 * 4);
  __syncthreads();

  // gate accumulators: row grow, experts gelo..gelo+3
  const int grow = tid & 127;
  const int gelo = (tid >> 7) * 4;
  float gacc[4] = {0.f, 0.f, 0.f, 0.f};

  // tower accumulators, live across all experts: M32 x T32 per warp
  float z[2][4][4];
#pragma unroll
  for (int a = 0; a < 2; ++a)
#pragma unroll
    for (int b = 0; b < 4; ++b)
#pragma unroll
      for (int k = 0; k < 4; ++k) z[a][b][k] = 0.f;

  for (int e = 0; e < E_N; ++e) {
    const float* Wbase = We + (size_t)e * H_N * D_IN;

    // ---- expert accumulators M64 x N64 ----
    float acc[4][8][4];
#pragma unroll
    for (int a = 0; a < 4; ++a)
#pragma unroll
      for (int b = 0; b < 8; ++b)
#pragma unroll
        for (int k = 0; k < 4; ++k) acc[a][b][k] = 0.f;

    // ---- prologue: issue chunk 0 into buf0 ----
    {
#pragma unroll
      for (int it = 0; it < 4; ++it) {
        int i = tid + it * NT, r = i >> 3, j4 = i & 7;
        cp16(sb + OFF_A0 + r * 144 + j4 * 16, Abase + (size_t)r * D_IN + j4 * 4);
      }
#pragma unroll
      for (int it = 0; it < 8; ++it) {
        int i = tid + it * NT, r = i >> 3, j4 = i & 7;
        cp16(sb + OFF_W0 + r * 144 + j4 * 16, Wbase + (size_t)r * D_IN + j4 * 4);
      }
      cp_commit();
    }

    for (int c = 0; c < NCH; ++c) {
      // issue chunk c+1 into buf (c+1)&1
      if (c + 1 < NCH) {
        const uint32_t ab = ((c + 1) & 1) ? (sb + OFF_A1) : (sb + OFF_A0);
        const uint32_t wb = ((c + 1) & 1) ? (sb + OFF_W1) : (sb + OFF_W0);
        const int k0 = (c + 1) * KC;
#pragma unroll
        for (int it = 0; it < 4; ++it) {
          int i = tid + it * NT, r = i >> 3, j4 = i & 7;
          cp16(ab + r * 144 + j4 * 16, Abase + (size_t)r * D_IN + k0 + j4 * 4);
        }
#pragma unroll
        for (int it = 0; it < 8; ++it) {
          int i = tid + it * NT, r = i >> 3, j4 = i & 7;
          cp16(wb + r * 144 + j4 * 16, Wbase + (size_t)r * D_IN + k0 + j4 * 4);
        }
        cp_commit();
        cp_wait<1>();
      } else {
        cp_wait<0>();
      }
      __syncthreads();

      const float* Asf = (const float*)(smem + ((c & 1) ? OFF_A1 : OFF_A0));
      const float* Wsf = (const float*)(smem + ((c & 1) ? OFF_W1 : OFF_W0));

      // gate partials (expert 0 only) from raw fp32 A
      if (e == 0) {
#pragma unroll
        for (int j4 = 0; j4 < 8; ++j4) {
          float4 x = *(const float4*)(Asf + grow * 36 + j4 * 4);
#pragma unroll
          for (int q = 0; q < 4; ++q) {
            const float* wrow = (const float*)(smem + OFF_WG) +
                                (gelo + q) * D_IN + c * KC + j4 * 4;
            gacc[q] += x.x * wrow[0] + x.y * wrow[1] + x.z * wrow[2] + x.w * wrow[3];
          }
        }
      }

      // compute: 4 k-steps of m16n8k8, warp tile M64 x N64
#pragma unroll
      for (int ks = 0; ks < 4; ++ks) {
        const int kk = ks * 8;
        uint32_t a[4][4];
#pragma unroll
        for (int mt = 0; mt < 4; ++mt) {
          const int r = wm * 64 + mt * 16;
          a[mt][0] = f2tf(Asf[(r + g) * 36 + kk + t4]);
          a[mt][1] = f2tf(Asf[(r + g + 8) * 36 + kk + t4]);
          a[mt][2] = f2tf(Asf[(r + g) * 36 + kk + t4 + 4]);
          a[mt][3] = f2tf(Asf[(r + g + 8) * 36 + kk + t4 + 4]);
        }
#pragma unroll
        for (int nt = 0; nt < 8; ++nt) {
          const int n = wn * 64 + nt * 8 + g;
          const uint32_t b0 = f2tf(Wsf[n * 36 + kk + t4]);
          const uint32_t b1 = f2tf(Wsf[n * 36 + kk + t4 + 4]);
#pragma unroll
          for (int mt = 0; mt < 4; ++mt)
            mma_s(acc[mt][nt][0], acc[mt][nt][1], acc[mt][nt][2], acc[mt][nt][3],
                  a[mt][0], a[mt][1], a[mt][2], a[mt][3], b0, b1);
        }
      }
      __syncthreads();  // all reads of buf c&1 done before it is refilled
    }

    // ---- gate softmax after expert 0 mainloop ----
    if (e == 0) {
#pragma unroll
      for (int q = 0; q < 4; ++q)
        gsm[grow * 8 + gelo + q] = gacc[q] + bg[gelo + q];
      __syncthreads();
      if (tid < BM) {
        float l[E_N], mx = -1e30f;
#pragma unroll
        for (int i = 0; i < E_N; ++i) { l[i] = gsm[tid * 8 + i]; mx = fmaxf(mx, l[i]); }
        float s = 0.f;
#pragma unroll
        for (int i = 0; i < E_N; ++i) { l[i] = __expf(l[i] - mx); s += l[i]; }
        float inv = 1.0f / s;
#pragma unroll
        for (int i = 0; i < E_N; ++i) gsm[tid * 8 + i] = l[i] * inv;
      }
      __syncthreads();
    }

    // ---- epilogue: Y = gate * relu(acc + be) as tf32 into smem ----
    const float* be_e = be + (size_t)e * H_N;
#pragma unroll
    for (int mt = 0; mt < 4; ++mt) {
      const int ra = wm * 64 + mt * 16 + g;
      const int rb = ra + 8;
      const float gva = gsm[ra * 8 + e];
      const float gvb = gsm[rb * 8 + e];
#pragma unroll
      for (int nt = 0; nt < 8; ++nt) {
        const int col = wn * 64 + nt * 8 + 2 * t4;
        const float b0 = be_e[col], b1 = be_e[col + 1];
        uint2 pa, pb;
        pa.x = f2tf(fmaxf(acc[mt][nt][0] + b0, 0.f) * gva);
        pa.y = f2tf(fmaxf(acc[mt][nt][1] + b1, 0.f) * gva);
        pb.x = f2tf(fmaxf(acc[mt][nt][2] + b0, 0.f) * gvb);
        pb.y = f2tf(fmaxf(acc[mt][nt][3] + b1, 0.f) * gvb);
        *(uint2*)(Yw + ra * 260 + col) = pa;
        *(uint2*)(Yw + rb * 260 + col) = pb;
      }
    }
    __syncthreads();

    // ---- tower: z += Y @ Wt^T (K=256), warp tile M32 x T32 ----
#pragma unroll 4
    for (int ks = 0; ks < 32; ++ks) {
      const int kk = ks * 8;
      uint32_t ta[2][4];
#pragma unroll
      for (int mt = 0; mt < 2; ++mt) {
        const int r = twm * 32 + mt * 16;
        ta[mt][0] = Ysu[(r + g) * 260 + kk + t4];
        ta[mt][1] = Ysu[(r + g + 8) * 260 + kk + t4];
        ta[mt][2] = Ysu[(r + g) * 260 + kk + t4 + 4];
        ta[mt][3] = Ysu[(r + g + 8) * 260 + kk + t4 + 4];
      }
#pragma unroll
      for (int nt = 0; nt < 4; ++nt) {
        const int n = twn * 32 + nt * 8 + g;
        const uint32_t b0 = WTu[n * 260 + kk + t4];
        const uint32_t b1 = WTu[n * 260 + kk + t4 + 4];
#pragma unroll
        for (int mt = 0; mt < 2; ++mt)
          mma_s(z[mt][nt][0], z[mt][nt][1], z[mt][nt][2], z[mt][nt][3],
                ta[mt][0], ta[mt][1], ta[mt][2], ta[mt][3], b0, b1);
      }
    }
    __syncthreads();  // Y (and underlying chunk bufs) free for next expert
  }

  // ---- final: out = sigmoid(z + bt) ----
#pragma unroll
  for (int mt = 0; mt < 2; ++mt) {
    const int ra = twm * 32 + mt * 16 + g;
    const int rb = ra + 8;
#pragma unroll
    for (int nt = 0; nt < 4; ++nt) {
      const int col = twn * 32 + nt * 8 + 2 * t4;
      const float b0 = bt[col], b1 = bt[col + 1];
      float2 va, vb;
      va.x = sigmoidf_(z[mt][nt][0] + b0);
      va.y = sigmoidf_(z[mt][nt][1] + b1);
      vb.x = sigmoidf_(z[mt][nt][2] + b0);
      vb.y = sigmoidf_(z[mt][nt][3] + b1);
      *(float2*)(out + (size_t)(row0 + ra) * T_N + col) = va;
      *(float2*)(out + (size_t)(row0 + rb) * T_N + col) = vb;
    }
  }
}

extern "C" void kernel_launch(void* const* d_in, const int* in_sizes, int n_in,
                              void* d_out, int out_size) {
  const float* xv = (const float*)d_in[0];
  const float* We = (const float*)d_in[1];
  const float* be = (const float*)d_in[2];
  const float* Wg = (const float*)d_in[3];
  const float* bg = (const float*)d_in[4];
  const float* Wt = (const float*)d_in[5];
  const float* bt = (const float*)d_in[6];
  float* out = (float*)d_out;

  const int B = in_sizes[0] / D_IN;  // 16384
  const int grid = B / BM;           // 128

  static int attr_set = 0;
  if (!attr_set) {
    cudaFuncSetAttribute(mmoe_fused_kernel,
                         cudaFuncAttributeMaxDynamicSharedMemorySize, SMEM_SZ);
    attr_set = 1;
  }
  mmoe_fused_kernel<<<grid, NT, SMEM_SZ>>>(xv, We, be, Wg, bg, Wt, bt, out);
}